// round 2
// baseline (speedup 1.0000x reference)
#include <cuda_runtime.h>

// Problem constants
#define NB      4
#define NDET    128
#define NT      2048
#define NPIX    65536            // 256*256
#define DC      4                // dets per chunk (SMEM = DC*NT*16B = 128KB)
#define NCHUNK  32               // NDET / DC
#define G       4                // chunks accumulated per block
#define SLOTS   8                // NCHUNK / G partial slots
#define PT      32               // pixel tiles
#define PPT     2048             // NPIX / PT
#define THREADS 512
#define PPTH    4                // pixels per thread = PPT / THREADS

// Scratch (static __device__ — no allocations allowed)
__device__ uint4  g_lutP[NCHUNK * NPIX];  // 16 MB packed lut, [chunk][pixel] -> 4 dets
__device__ float4 g_part[SLOTS * NPIX];   // 8 MB partials [slot][pixel] -> per-batch

// ---------------------------------------------------------------------------
// Pack one (k_floor, alpha) pair: bits[0:11)=k0 (clamped 0..2046),
// bit[11]=valid, bits[12:32)=alpha in 2^-20 fixed point.
// ---------------------------------------------------------------------------
__device__ __forceinline__ unsigned pack_lut(float kf, float a) {
    int k = (int)kf;
    unsigned valid = ((unsigned)k < 2047u) ? 1u : 0u;   // 0 <= k < NT-1
    int k0 = min(max(k, 0), NT - 2);
    unsigned aq = (unsigned)(a * 1048576.0f);
    if (aq > 1048575u) aq = 1048575u;
    return (unsigned)k0 | (valid << 11) | (aq << 12);
}

// ---------------------------------------------------------------------------
// Kernel 1: pack + transpose lut [pixel][det][2f] -> [chunk][pixel] uint4.
// Reads fully coalesced (linear float4), SMEM tile transpose, writes in
// 128B runs. 64 MB read (DRAM floor), 16 MB write.
// ---------------------------------------------------------------------------
__global__ void __launch_bounds__(THREADS)
lut_pack_kernel(const float4* __restrict__ lut4) {
    __shared__ uint2 tile[8][64];           // [p_local][det-pair f]  4 KB
    const int t = threadIdx.x;
    const size_t base = (size_t)blockIdx.x * THREADS;   // covers 8 pixels x 64 f

    float4 v = lut4[base + t];              // dets (2f, 2f+1) of pixel p
    int p_local = t >> 6;                   // t / 64
    int f       = t & 63;
    uint2 u;
    u.x = pack_lut(v.x, v.y);
    u.y = pack_lut(v.z, v.w);
    tile[p_local][f] = u;
    __syncthreads();

    if (t < 256) {
        int c4 = t >> 3;                    // chunk 0..31
        int pl = t & 7;
        uint2 a = tile[pl][2 * c4];
        uint2 b = tile[pl][2 * c4 + 1];
        size_t p = (size_t)blockIdx.x * 8 + pl;
        g_lutP[(size_t)c4 * NPIX + p] = make_uint4(a.x, a.y, b.x, b.y);
    }
}

// ---------------------------------------------------------------------------
// Kernel 2: main backprojection.
// grid = (PT pixel-tiles, SLOTS). Each block loops over G chunks: stage DC
// det rows (on-the-fly transpose from original sino, float4-over-batch),
// then each thread processes 4 pixels with one coalesced packed-lut LDG.128
// and 2 LDS.128 gathers per det. Accumulate G chunks in registers.
// ---------------------------------------------------------------------------
extern __shared__ float4 s_sino[];   // [DC][NT]  128 KB

__global__ void __launch_bounds__(THREADS, 1)
bp_main_kernel(const float* __restrict__ sino) {
    const int tid   = threadIdx.x;
    const int pbase = blockIdx.x * PPT;
    const int slot  = blockIdx.y;

    float4 acc[PPTH];
    #pragma unroll
    for (int pp = 0; pp < PPTH; pp++) acc[pp] = make_float4(0.f, 0.f, 0.f, 0.f);

    for (int g = 0; g < G; g++) {
        const int c = slot * G + g;
        __syncthreads();   // protect SMEM reuse from previous iteration

        // Stage DC det rows, transposing batches into float4 on the fly.
        // 4 coalesced LDG.32 + 1 conflict-free STS.128 per entry.
        #pragma unroll 4
        for (int i = tid; i < DC * NT; i += THREADS) {
            int j = i >> 11;            // det within chunk
            int k = i & (NT - 1);
            const float* sp = sino + (size_t)(c * DC + j) * NT + k;
            float4 v;
            v.x = sp[0 * NDET * NT];
            v.y = sp[1 * NDET * NT];
            v.z = sp[2 * NDET * NT];
            v.w = sp[3 * NDET * NT];
            s_sino[i] = v;
        }

        // Hann weights for this chunk's dets.
        float apod[DC];
        #pragma unroll
        for (int j = 0; j < DC; j++) {
            int d = c * DC + j;
            apod[j] = 0.5f - 0.5f * cosf(6.2831853071795864769f * (float)d / 127.0f);
        }

        __syncthreads();

        const uint4* __restrict__ lp = g_lutP + (size_t)c * NPIX + pbase;

        #pragma unroll
        for (int pp = 0; pp < PPTH; pp++) {
            uint4 L = lp[pp * THREADS + tid];      // coalesced LDG.128
            unsigned u[DC] = {L.x, L.y, L.z, L.w};

            #pragma unroll
            for (int j = 0; j < DC; j++) {
                unsigned v = u[j];
                int   k0 = v & 0x7FF;                       // 0..2046
                float w  = ((v >> 11) & 1u) ? apod[j] : 0.0f;
                float a  = (float)(v >> 12) * (1.0f / 1048576.0f);

                float4 s0 = s_sino[j * NT + k0];
                float4 s1 = s_sino[j * NT + k0 + 1];

                float wa = w * a;
                float w0 = w - wa;
                acc[pp].x = fmaf(w0, s0.x, fmaf(wa, s1.x, acc[pp].x));
                acc[pp].y = fmaf(w0, s0.y, fmaf(wa, s1.y, acc[pp].y));
                acc[pp].z = fmaf(w0, s0.z, fmaf(wa, s1.z, acc[pp].z));
                acc[pp].w = fmaf(w0, s0.w, fmaf(wa, s1.w, acc[pp].w));
            }
        }
    }

    #pragma unroll
    for (int pp = 0; pp < PPTH; pp++) {
        g_part[(size_t)slot * NPIX + pbase + pp * THREADS + tid] = acc[pp];
    }
}

// ---------------------------------------------------------------------------
// Kernel 3: reduce 8 partial slots, normalize, write output (B,1,NY,NX).
// ---------------------------------------------------------------------------
__global__ void bp_reduce_kernel(float* __restrict__ out) {
    int p = blockIdx.x * blockDim.x + threadIdx.x;
    if (p >= NPIX) return;
    float4 acc = make_float4(0.f, 0.f, 0.f, 0.f);
    #pragma unroll
    for (int s = 0; s < SLOTS; s++) {
        float4 v = g_part[(size_t)s * NPIX + p];
        acc.x += v.x; acc.y += v.y; acc.z += v.z; acc.w += v.w;
    }
    // sum_d apod[d] = 64 - 0.5 * 1 = 63.5 exactly
    const float inv_norm = 1.0f / 63.5f;
    out[0 * NPIX + p] = acc.x * inv_norm;
    out[1 * NPIX + p] = acc.y * inv_norm;
    out[2 * NPIX + p] = acc.z * inv_norm;
    out[3 * NPIX + p] = acc.w * inv_norm;
}

// ---------------------------------------------------------------------------
extern "C" void kernel_launch(void* const* d_in, const int* in_sizes, int n_in,
                              void* d_out, int out_size) {
    const float*  sino = (const float*)d_in[0];
    const float4* lut4 = (const float4*)d_in[1];
    float*        out  = (float*)d_out;

    cudaFuncSetAttribute(bp_main_kernel,
                         cudaFuncAttributeMaxDynamicSharedMemorySize,
                         DC * NT * (int)sizeof(float4));

    // 65536 px * 64 float4 / 512 threads = 8192 blocks
    lut_pack_kernel<<<(NPIX * 64) / THREADS, THREADS>>>(lut4);

    dim3 grid(PT, SLOTS);
    bp_main_kernel<<<grid, THREADS, DC * NT * sizeof(float4)>>>(sino);

    bp_reduce_kernel<<<(NPIX + 255) / 256, 256>>>(out);
}

// round 5
// speedup vs baseline: 1.4033x; 1.4033x over previous
#include <cuda_runtime.h>

// Problem constants
#define NB      4
#define NDET    128
#define NT      2048
#define NPIX    65536            // 256*256
#define DC      4                // dets per chunk (SMEM = DC*NT*16B = 128KB)
#define NCHUNK  32               // NDET / DC
#define PT      8                // pixel tiles
#define PPT     8192             // NPIX / PT
#define THREADS 1024
#define PPTH    8                // pixels per thread = PPT / THREADS

// Scratch (static __device__ — no allocations allowed)
__device__ float4 g_part[NCHUNK * NPIX];  // 32 MB partials [chunk][pixel] -> per-batch

// ---------------------------------------------------------------------------
// Main backprojection kernel.
// grid = (PT, NCHUNK) = 256 blocks x 1024 threads, 128 KB dynamic SMEM.
// Each block: stage 4 det rows (all 4 batches -> float4 per k, on-the-fly
// transpose from raw sino, all L2-resident), one __syncthreads, then each
// thread handles 8 pixels: 2 x LDG.128 lut (one aligned 32B sector), then
// per det 2 x LDS.128 gathers + 8 FMA. Writes one float4 partial per pixel.
// Deterministic (no atomics).
// ---------------------------------------------------------------------------
extern __shared__ float4 s_sino[];   // [DC][NT]  128 KB

__global__ void __launch_bounds__(THREADS, 1)
bp_main_kernel(const float* __restrict__ sino,
               const float4* __restrict__ lut4) {
    const int tid   = threadIdx.x;
    const int pbase = blockIdx.x * PPT;
    const int c     = blockIdx.y;          // det chunk

    // Stage DC det rows, transposing batches into float4 on the fly.
    // 8 float4 per thread, each = 4 coalesced LDG.32 (L2 hits) + 1 STS.128.
    #pragma unroll 8
    for (int i = tid; i < DC * NT; i += THREADS) {
        int j = i >> 11;            // det within chunk
        int k = i & (NT - 1);
        const float* sp = sino + (size_t)(c * DC + j) * NT + k;
        float4 v;
        v.x = __ldg(sp + 0 * NDET * NT);
        v.y = __ldg(sp + 1 * NDET * NT);
        v.z = __ldg(sp + 2 * NDET * NT);
        v.w = __ldg(sp + 3 * NDET * NT);
        s_sino[i] = v;
    }

    // Hann window weights for this chunk's 4 dets (norm applied at reduce).
    float apod[DC];
    #pragma unroll
    for (int j = 0; j < DC; j++) {
        int d = c * DC + j;
        apod[j] = 0.5f - 0.5f * cosf(6.2831853071795864769f * (float)d / 127.0f);
    }

    __syncthreads();

    float4* __restrict__ part = g_part + (size_t)c * NPIX + pbase;

    #pragma unroll 2
    for (int pp = 0; pp < PPTH; pp++) {
        const int pl = pp * THREADS + tid;        // pixel within tile
        const size_t p = (size_t)(pbase + pl);

        // lut layout: [pixel][det][2] floats -> 64 float4 per pixel.
        // This chunk's 4 dets = 2 adjacent float4 (one aligned 32B sector).
        const size_t lbase = p * 64 + (size_t)c * 2;
        float4 la = __ldg(lut4 + lbase);
        float4 lb = __ldg(lut4 + lbase + 1);

        float kf[DC] = {la.x, la.z, lb.x, lb.z};
        float al[DC] = {la.y, la.w, lb.y, lb.w};

        float4 acc = make_float4(0.f, 0.f, 0.f, 0.f);

        #pragma unroll
        for (int j = 0; j < DC; j++) {
            int k = (int)kf[j];
            bool valid = ((unsigned)k < (unsigned)(NT - 1));   // 0 <= k < NT-1
            int k0 = min(max(k, 0), NT - 2);

            float4 s0 = s_sino[j * NT + k0];
            float4 s1 = s_sino[j * NT + k0 + 1];

            float w  = valid ? apod[j] : 0.0f;
            float wa = w * al[j];
            float w0 = w - wa;

            acc.x = fmaf(w0, s0.x, fmaf(wa, s1.x, acc.x));
            acc.y = fmaf(w0, s0.y, fmaf(wa, s1.y, acc.y));
            acc.z = fmaf(w0, s0.z, fmaf(wa, s1.z, acc.z));
            acc.w = fmaf(w0, s0.w, fmaf(wa, s1.w, acc.w));
        }

        part[pl] = acc;    // coalesced float4 store
    }
}

// ---------------------------------------------------------------------------
// Reduce partials over 32 chunks, normalize, write output (B,1,NY,NX).
// ---------------------------------------------------------------------------
__global__ void __launch_bounds__(256)
bp_reduce_kernel(float* __restrict__ out) {
    int p = blockIdx.x * blockDim.x + threadIdx.x;
    if (p >= NPIX) return;
    float4 acc = make_float4(0.f, 0.f, 0.f, 0.f);
    #pragma unroll 8
    for (int c = 0; c < NCHUNK; c++) {
        float4 v = __ldg(&g_part[(size_t)c * NPIX + p]);
        acc.x += v.x; acc.y += v.y; acc.z += v.z; acc.w += v.w;
    }
    // sum_d apod[d] = 64 - 0.5 * (geometric cos sum = 1) = 63.5 exactly
    const float inv_norm = 1.0f / 63.5f;
    out[0 * NPIX + p] = acc.x * inv_norm;
    out[1 * NPIX + p] = acc.y * inv_norm;
    out[2 * NPIX + p] = acc.z * inv_norm;
    out[3 * NPIX + p] = acc.w * inv_norm;
}

// ---------------------------------------------------------------------------
extern "C" void kernel_launch(void* const* d_in, const int* in_sizes, int n_in,
                              void* d_out, int out_size) {
    const float*  sino = (const float*)d_in[0];
    const float4* lut4 = (const float4*)d_in[1];
    float*        out  = (float*)d_out;

    cudaFuncSetAttribute(bp_main_kernel,
                         cudaFuncAttributeMaxDynamicSharedMemorySize,
                         DC * NT * (int)sizeof(float4));

    dim3 grid(PT, NCHUNK);
    bp_main_kernel<<<grid, THREADS, DC * NT * sizeof(float4)>>>(sino, lut4);

    bp_reduce_kernel<<<(NPIX + 255) / 256, 256>>>(out);
}